// round 13
// baseline (speedup 1.0000x reference)
#include <cuda_runtime.h>

#define NN   4096
#define FEAT 1024
#define GC   10
#define HD   5

typedef unsigned long long u64;

// Scratch (no allocations allowed)
__device__ float g_s[NN];
__device__ float g_Ma[NN * GC];
__device__ float g_Mb[NN * GC];
__device__ float g_Hp[NN * 12];
__device__ float g_hfin[32];
__device__ float g_cfin[32];

__device__ __forceinline__ float tanha(float x) {
    float y;
    asm("tanh.approx.f32 %0, %1;" : "=f"(y) : "f"(x));
    return y;
}
__device__ __forceinline__ float siga(float x) {
    return fmaf(0.5f, tanha(0.5f * x), 0.5f);
}
__device__ __forceinline__ float seluf(float v) {
    return v > 0.0f ? 1.0507009873554805f * v
                    : 1.7580993408473766f * (__expf(v) - 1.0f);
}
// ---- f32x2 packed helpers ----
__device__ __forceinline__ u64 pk2(float lo, float hi) {
    u64 r; asm("mov.b64 %0, {%1, %2};" : "=l"(r) : "f"(lo), "f"(hi)); return r;
}
__device__ __forceinline__ void upk2(float& lo, float& hi, u64 v) {
    asm("mov.b64 {%0, %1}, %2;" : "=f"(lo), "=f"(hi) : "l"(v));
}
__device__ __forceinline__ u64 fma2(u64 a, u64 b, u64 c) {
    u64 d; asm("fma.rn.f32x2 %0, %1, %2, %3;" : "=l"(d) : "l"(a), "l"(b), "l"(c));
    return d;
}
__device__ __forceinline__ u64 add2(u64 a, u64 b) {
    u64 d; asm("add.rn.f32x2 %0, %1, %2;" : "=l"(d) : "l"(a), "l"(b));
    return d;
}

// ---------------------------------------------------------------------------
// K1: fused rowsum (blocks 0..NN-1) + X@W0^T (blocks NN..NN+511)
// ---------------------------------------------------------------------------
__global__ void k_pre(const float* __restrict__ A, const float* __restrict__ X,
                      const float* __restrict__ W0) {
    if (blockIdx.x < NN) {
        int row = blockIdx.x;
        const float4* a4 = (const float4*)(A + (size_t)row * NN);
        float s = 0.0f;
        for (int i = threadIdx.x; i < NN / 4; i += blockDim.x) {
            float4 v = a4[i];
            s += (v.x + v.y) + (v.z + v.w);
        }
        __shared__ float red[8];
        #pragma unroll
        for (int o = 16; o; o >>= 1) s += __shfl_xor_sync(0xffffffffu, s, o);
        if ((threadIdx.x & 31) == 0) red[threadIdx.x >> 5] = s;
        __syncthreads();
        if (threadIdx.x < 32) {
            float v = (threadIdx.x < (blockDim.x >> 5)) ? red[threadIdx.x] : 0.0f;
            #pragma unroll
            for (int o = 4; o; o >>= 1) v += __shfl_xor_sync(0xffffffffu, v, o);
            if (threadIdx.x == 0) g_s[row] = v > 0.0f ? rsqrtf(v) : 0.0f;
        }
    } else {
        int row  = (blockIdx.x - NN) * 8 + (threadIdx.x >> 5);
        int lane = threadIdx.x & 31;
        const float* xr = X + (size_t)row * FEAT;
        float acc[GC];
        #pragma unroll
        for (int k = 0; k < GC; k++) acc[k] = 0.0f;
        for (int m = 0; m < FEAT / 32; m++) {
            int j = m * 32 + lane;
            float xv = xr[j];
            #pragma unroll
            for (int k = 0; k < GC; k++) acc[k] += xv * W0[k * FEAT + j];
        }
        #pragma unroll
        for (int k = 0; k < GC; k++) {
            #pragma unroll
            for (int o = 16; o; o >>= 1)
                acc[k] += __shfl_xor_sync(0xffffffffu, acc[k], o);
        }
        if (lane == 0) {
            #pragma unroll
            for (int k = 0; k < GC; k++) g_Ma[row * GC + k] = acc[k];
        }
    }
}

// ---------------------------------------------------------------------------
// K2: out = selu(Ahat @ in) [@ W^T if STAGE<2, else padded stride-12 write]
// 256 threads, 16 rows/block (proven best occupancy), float4 A loads for MLP.
// ---------------------------------------------------------------------------
#define RPB 16
#define JC  1024
template <int STAGE>
__global__ void k_spmm(const float* __restrict__ A, const float* __restrict__ W) {
    const float* in  = (STAGE == 1) ? g_Mb : g_Ma;
    __shared__ __align__(16) float Zs[JC * 12];
    int rowbase = blockIdx.x * RPB;
    int sub = threadIdx.x & 15;
    int r   = threadIdx.x >> 4;
    int row = rowbase + r;
    float acc[GC];
    #pragma unroll
    for (int k = 0; k < GC; k++) acc[k] = 0.0f;

    for (int jb = 0; jb < NN; jb += JC) {
        __syncthreads();
        for (int t = threadIdx.x; t < JC; t += blockDim.x) {
            int j = jb + t;
            float sj = g_s[j];
            #pragma unroll
            for (int k = 0; k < GC; k++) Zs[t * 12 + k] = sj * in[j * GC + k];
        }
        __syncthreads();
        const float4* ar4 = (const float4*)(A + (size_t)row * NN + jb);
        #pragma unroll 2
        for (int m = 0; m < JC / 64; m++) {
            int jj4 = sub + m * 16;
            float4 av = ar4[jj4];
            int j0 = jj4 * 4;
            float a4v[4] = {av.x, av.y, av.z, av.w};
            #pragma unroll
            for (int e = 0; e < 4; e++) {
                float a = a4v[e];
                const float* zr = &Zs[(j0 + e) * 12];
                float4 z0 = *(const float4*)zr;
                float4 z1 = *(const float4*)(zr + 4);
                float2 z2 = *(const float2*)(zr + 8);
                acc[0] += a * z0.x; acc[1] += a * z0.y;
                acc[2] += a * z0.z; acc[3] += a * z0.w;
                acc[4] += a * z1.x; acc[5] += a * z1.y;
                acc[6] += a * z1.z; acc[7] += a * z1.w;
                acc[8] += a * z2.x; acc[9] += a * z2.y;
            }
        }
    }
    #pragma unroll
    for (int k = 0; k < GC; k++) {
        #pragma unroll
        for (int o = 8; o; o >>= 1)
            acc[k] += __shfl_xor_sync(0xffffffffu, acc[k], o);
    }
    if (sub == 0) {
        float si = g_s[row];
        float sv[GC];
        #pragma unroll
        for (int k = 0; k < GC; k++) {
            float v = si * acc[k] + si * si * in[row * GC + k];
            sv[k] = seluf(v);
        }
        if (STAGE < 2) {
            float* out = (STAGE == 0) ? g_Mb : g_Ma;
            #pragma unroll
            for (int ko = 0; ko < GC; ko++) {
                float s = 0.0f;
                #pragma unroll
                for (int k = 0; k < GC; k++) s = fmaf(sv[k], W[ko * GC + k], s);
                out[row * GC + ko] = s;
            }
        } else {
            #pragma unroll
            for (int k = 0; k < GC; k++) g_Hp[row * 12 + k] = sv[k];
        }
    }
}

// ---------------------------------------------------------------------------
// K3: encoder — wavefront pipeline, packed gate dots, recurrent precomputed.
// Sigmoid input scale (0.5) folded into the i/f/o weight rows at load time:
// sigmoid(x) = 0.5*tanh(0.5x)+0.5 needs no pre-mul when weights are halved.
// ---------------------------------------------------------------------------
__global__ void __launch_bounds__(32, 1) k_enc(
    const float* __restrict__ Wih_g, const float* __restrict__ Whh_g,
    const float* __restrict__ bih_g, const float* __restrict__ bhh_g,
    const float* __restrict__ h0_g,  const float* __restrict__ c0_g)
{
    const int lane = threadIdx.x;
    const unsigned FM = 0xffffffffu;
    const int li   = (lane < 30) ? lane : 29;
    const int myl  = li / 10;
    const int rr   = li % 10;
    const int dsel = rr / 5;
    const int j    = rr % 5;
    const int kc   = 2 * myl + dsel;

    const int rI = kc * 20 + j, rF = rI + 5, rG = rI + 10, rO = rI + 15;
    u64 wIF[GC], wGO[GC], vIF[HD], vGO[HD];
    #pragma unroll
    for (int i = 0; i < GC; i++) {
        wIF[i] = pk2(0.5f * Wih_g[rI * GC + i], 0.5f * Wih_g[rF * GC + i]);
        wGO[i] = pk2(Wih_g[rG * GC + i], 0.5f * Wih_g[rO * GC + i]);
    }
    #pragma unroll
    for (int i = 0; i < HD; i++) {
        vIF[i] = pk2(0.5f * Whh_g[rI * HD + i], 0.5f * Whh_g[rF * HD + i]);
        vGO[i] = pk2(Whh_g[rG * HD + i], 0.5f * Whh_g[rO * HD + i]);
    }
    const u64 bIF = pk2(0.5f * (bih_g[rI] + bhh_g[rI]),
                        0.5f * (bih_g[rF] + bhh_g[rF]));
    const u64 bGO = pk2(bih_g[rG] + bhh_g[rG],
                        0.5f * (bih_g[rO] + bhh_g[rO]));

    float h = h0_g[kc * HD + j];
    float c = c0_g[kc * HD + j];
    float hp[HD];
    #pragma unroll
    for (int i = 0; i < HD; i++) hp[i] = h0_g[kc * HD + i];

    u64 rIF = bIF, rGO = bGO;
    #pragma unroll
    for (int i = 0; i < HD; i++) {
        u64 hpk = pk2(hp[i], hp[i]);
        rIF = fma2(vIF[i], hpk, rIF);
        rGO = fma2(vGO[i], hpk, rGO);
    }

    float xin[GC], buf[GC];
    u64 xpk[GC];
    #pragma unroll
    for (int i = 0; i < GC; i++) { xin[i] = g_Hp[i]; xpk[i] = pk2(xin[i], xin[i]); }
    #pragma unroll
    for (int i = 0; i < GC; i++) buf[i] = g_Hp[12 + i];

    const int pullbase = (myl == 0) ? 0 : (myl - 1) * 10;
    const int hpbase   = myl * 10 + dsel * 5;

    for (int w = 0; w < NN + 2; w++) {
        int nrow = (w + 2 < NN) ? (w + 2) : (NN - 1);
        float4 ra = *(const float4*)&g_Hp[nrow * 12];
        float4 rb = *(const float4*)&g_Hp[nrow * 12 + 4];
        float2 rc = *(const float2*)&g_Hp[nrow * 12 + 8];

        bool valid = (w >= myl) && (w - myl < NN);

        u64 s0 = rIF, s1 = 0ull, s2 = rGO, s3 = 0ull;
        #pragma unroll
        for (int i = 0; i < 5; i++) {
            s0 = fma2(wIF[i], xpk[i], s0);
            s2 = fma2(wGO[i], xpk[i], s2);
        }
        #pragma unroll
        for (int i = 5; i < 10; i++) {
            s1 = fma2(wIF[i], xpk[i], s1);
            s3 = fma2(wGO[i], xpk[i], s3);
        }
        u64 gIF = add2(s0, s1), gGO = add2(s2, s3);
        float gi, gf, gg, go;
        upk2(gi, gf, gIF);
        upk2(gg, go, gGO);
        // gi, gf, go are pre-halved via scaled weights
        float ai = fmaf(0.5f, tanha(gi), 0.5f);
        float af = fmaf(0.5f, tanha(gf), 0.5f);
        float ag = tanha(gg);
        float ao = fmaf(0.5f, tanha(go), 0.5f);
        float cn = fmaf(af, c, ai * ag);
        float hn = ao * tanha(cn);
        c = valid ? cn : c;
        h = valid ? hn : h;

        float pull[GC];
        #pragma unroll
        for (int m = 0; m < GC; m++)
            pull[m] = __shfl_sync(FM, h, pullbase + m);
        #pragma unroll
        for (int i = 0; i < HD; i++)
            hp[i] = __shfl_sync(FM, h, hpbase + i);

        #pragma unroll
        for (int m = 0; m < GC; m++) {
            xin[m] = (myl == 0) ? buf[m] : pull[m];
            xpk[m] = pk2(xin[m], xin[m]);
        }
        buf[0] = ra.x; buf[1] = ra.y; buf[2] = ra.z; buf[3] = ra.w;
        buf[4] = rb.x; buf[5] = rb.y; buf[6] = rb.z; buf[7] = rb.w;
        buf[8] = rc.x; buf[9] = rc.y;

        u64 t0 = bIF, t1 = bGO;
        #pragma unroll
        for (int i = 0; i < HD; i++) {
            u64 hpk = pk2(hp[i], hp[i]);
            t0 = fma2(vIF[i], hpk, t0);
            t1 = fma2(vGO[i], hpk, t1);
        }
        rIF = t0; rGO = t1;
    }

    if (lane < 30) {
        g_hfin[lane] = h;
        g_cfin[lane] = c;
    }
}

// ---------------------------------------------------------------------------
// K4: decoder — 20-lane layout, 2 gates/lane packed, recurrent hoisted.
// Sigmoid 0.5-scale folded into weights: A-half scaled 0.5 on gh=0 lanes
// (i-gate), B-half (f / o gates) scaled 0.5 always; g-gate (gh=1 A-half)
// keeps full scale for tanh.
// ---------------------------------------------------------------------------
__global__ void __launch_bounds__(32, 1) k_dec(
    const float* __restrict__ Wih_g, const float* __restrict__ Whh_g,
    const float* __restrict__ bih_g, const float* __restrict__ bhh_g,
    const float* __restrict__ tok_g, const float* __restrict__ Wo_g,
    const float* __restrict__ bo_g,  float* __restrict__ out)
{
    const int lane = threadIdx.x;
    const unsigned FM = 0xffffffffu;
    const int dl  = (lane < 20) ? lane : 19;
    const int pp  = dl % 10;
    const int gh  = dl / 10;   // 0: gates (i,f), 1: gates (g,o)
    const int dd  = pp / 5;
    const int jd  = pp % 5;
    const float sA = gh ? 1.0f : 0.5f;   // A-half input scale

    u64 wAB[3][GC], vAB[3][HD], bAB[3];
    #pragma unroll
    for (int l = 0; l < 3; l++) {
        int kc2  = 2 * l + dd;
        int rowA = kc2 * 20 + gh * 10 + jd;
        int rowB = rowA + 5;
        #pragma unroll
        for (int i = 0; i < GC; i++)
            wAB[l][i] = pk2(sA * Wih_g[rowA * GC + i], 0.5f * Wih_g[rowB * GC + i]);
        #pragma unroll
        for (int i = 0; i < HD; i++)
            vAB[l][i] = pk2(sA * Whh_g[rowA * HD + i], 0.5f * Whh_g[rowB * HD + i]);
        bAB[l] = pk2(sA * (bih_g[rowA] + bhh_g[rowA]),
                     0.5f * (bih_g[rowB] + bhh_g[rowB]));
    }
    float cD[3];
    u64 rAB[3];
    #pragma unroll
    for (int l = 0; l < 3; l++) {
        cD[l] = g_cfin[l * 10 + pp];
        u64 racc = bAB[l];
        #pragma unroll
        for (int i = 0; i < HD; i++) {
            float hv = g_hfin[l * 10 + dd * 5 + i];
            racc = fma2(vAB[l][i], pk2(hv, hv), racc);
        }
        rAB[l] = racc;
    }
    float wov[GC];
    #pragma unroll
    for (int i = 0; i < GC; i++) wov[i] = Wo_g[i];
    const float bo0 = bo_g[0];

    float xs[GC];
    u64 xpk[GC];
    #pragma unroll
    for (int i = 0; i < GC; i++) { xs[i] = tok_g[i]; xpk[i] = pk2(xs[i], xs[i]); }

    for (int t = 0; t < NN; t++) {
        #pragma unroll
        for (int l = 0; l < 3; l++) {
            // critical dot: 10 input terms, packed (A,B) gates
            u64 s0 = rAB[l], s1 = 0ull;
            #pragma unroll
            for (int i = 0; i < 5; i++) s0 = fma2(wAB[l][i], xpk[i], s0);
            #pragma unroll
            for (int i = 5; i < 10; i++) s1 = fma2(wAB[l][i], xpk[i], s1);
            u64 g2 = add2(s0, s1);
            float gA, gB;
            upk2(gA, gB, g2);
            // gh=0: A=i (sig, pre-halved), B=f (sig, pre-halved)
            // gh=1: A=g (tanh, full),      B=o (sig, pre-halved)
            float tA = tanha(gA);
            float aA = gh ? tA : fmaf(0.5f, tA, 0.5f);
            float aB = fmaf(0.5f, tanha(gB), 0.5f);
            float ag = __shfl_sync(FM, aA, 10 + pp);
            float ao = __shfl_sync(FM, aB, 10 + pp);
            float cn = fmaf(aB, cD[l], aA * ag);
            float hn = ao * tanha(cn);
            cD[l] = cn;
            #pragma unroll
            for (int m = 0; m < GC; m++) {
                xs[m] = __shfl_sync(FM, hn, m);
                xpk[m] = pk2(xs[m], xs[m]);
            }
            // precompute next step's recurrent for this layer (off crit path)
            u64 racc = bAB[l];
            #pragma unroll
            for (int i = 0; i < HD; i++) {
                u64 hx = dd ? xpk[5 + i] : xpk[i];
                racc = fma2(vAB[l][i], hx, racc);
            }
            rAB[l] = racc;
        }
        float z = bo0;
        #pragma unroll
        for (int i = 0; i < GC; i++) z = fmaf(xs[i], wov[i], z);
        if (lane == 0) out[t] = siga(z);
    }
}

// ---------------------------------------------------------------------------
extern "C" void kernel_launch(void* const* d_in, const int* in_sizes, int n_in,
                              void* d_out, int out_size)
{
    const float* A   = (const float*)d_in[0];
    const float* X   = (const float*)d_in[1];
    const float* W0  = (const float*)d_in[2];
    const float* W1  = (const float*)d_in[3];
    const float* W2  = (const float*)d_in[4];
    const float* Wih = (const float*)d_in[5];
    const float* Whh = (const float*)d_in[6];
    const float* bih = (const float*)d_in[7];
    const float* bhh = (const float*)d_in[8];
    const float* h0  = (const float*)d_in[9];
    const float* c0  = (const float*)d_in[10];
    const float* tok = (const float*)d_in[11];
    const float* Wo  = (const float*)d_in[12];
    const float* bo  = (const float*)d_in[13];
    float* out = (float*)d_out;
    (void)in_sizes; (void)n_in; (void)out_size;

    k_pre<<<NN + 512, 256>>>(A, X, W0);        // g_s + g_Ma = X@W0^T
    k_spmm<0><<<NN / RPB, 256>>>(A, W1);       // g_Mb = selu(Ahat@g_Ma)@W1^T
    k_spmm<1><<<NN / RPB, 256>>>(A, W2);       // g_Ma = selu(Ahat@g_Mb)@W2^T
    k_spmm<2><<<NN / RPB, 256>>>(A, nullptr);  // g_Hp = H3 (padded)
    k_enc<<<1, 32>>>(Wih, Whh, bih, bhh, h0, c0);
    k_dec<<<1, 32>>>(Wih, Whh, bih, bhh, tok, Wo, bo, out);
}

// round 14
// speedup vs baseline: 1.0592x; 1.0592x over previous
#include <cuda_runtime.h>

#define NN   4096
#define FEAT 1024
#define GC   10
#define HD   5

typedef unsigned long long u64;

// Scratch (no allocations allowed)
__device__ float g_s[NN];
__device__ float g_Ma[NN * GC];
__device__ float g_Mb[NN * GC];
__device__ float g_Hp[NN * 12];
__device__ float g_hfin[32];
__device__ float g_cfin[32];

__device__ __forceinline__ float tanha(float x) {
    float y;
    asm("tanh.approx.f32 %0, %1;" : "=f"(y) : "f"(x));
    return y;
}
__device__ __forceinline__ float siga(float x) {
    return fmaf(0.5f, tanha(0.5f * x), 0.5f);
}
__device__ __forceinline__ float seluf(float v) {
    return v > 0.0f ? 1.0507009873554805f * v
                    : 1.7580993408473766f * (__expf(v) - 1.0f);
}
// ---- f32x2 packed helpers ----
__device__ __forceinline__ u64 pk2(float lo, float hi) {
    u64 r; asm("mov.b64 %0, {%1, %2};" : "=l"(r) : "f"(lo), "f"(hi)); return r;
}
__device__ __forceinline__ void upk2(float& lo, float& hi, u64 v) {
    asm("mov.b64 {%0, %1}, %2;" : "=f"(lo), "=f"(hi) : "l"(v));
}
__device__ __forceinline__ u64 fma2(u64 a, u64 b, u64 c) {
    u64 d; asm("fma.rn.f32x2 %0, %1, %2, %3;" : "=l"(d) : "l"(a), "l"(b), "l"(c));
    return d;
}
__device__ __forceinline__ u64 add2(u64 a, u64 b) {
    u64 d; asm("add.rn.f32x2 %0, %1, %2;" : "=l"(d) : "l"(a), "l"(b));
    return d;
}

// ---------------------------------------------------------------------------
// K1: fused rowsum (blocks 0..NN-1) + X@W0^T (blocks NN..NN+511)
// ---------------------------------------------------------------------------
__global__ void k_pre(const float* __restrict__ A, const float* __restrict__ X,
                      const float* __restrict__ W0) {
    if (blockIdx.x < NN) {
        int row = blockIdx.x;
        const float4* a4 = (const float4*)(A + (size_t)row * NN);
        float s = 0.0f;
        for (int i = threadIdx.x; i < NN / 4; i += blockDim.x) {
            float4 v = a4[i];
            s += (v.x + v.y) + (v.z + v.w);
        }
        __shared__ float red[8];
        #pragma unroll
        for (int o = 16; o; o >>= 1) s += __shfl_xor_sync(0xffffffffu, s, o);
        if ((threadIdx.x & 31) == 0) red[threadIdx.x >> 5] = s;
        __syncthreads();
        if (threadIdx.x < 32) {
            float v = (threadIdx.x < (blockDim.x >> 5)) ? red[threadIdx.x] : 0.0f;
            #pragma unroll
            for (int o = 4; o; o >>= 1) v += __shfl_xor_sync(0xffffffffu, v, o);
            if (threadIdx.x == 0) g_s[row] = v > 0.0f ? rsqrtf(v) : 0.0f;
        }
    } else {
        int row  = (blockIdx.x - NN) * 8 + (threadIdx.x >> 5);
        int lane = threadIdx.x & 31;
        const float* xr = X + (size_t)row * FEAT;
        float acc[GC];
        #pragma unroll
        for (int k = 0; k < GC; k++) acc[k] = 0.0f;
        for (int m = 0; m < FEAT / 32; m++) {
            int j = m * 32 + lane;
            float xv = xr[j];
            #pragma unroll
            for (int k = 0; k < GC; k++) acc[k] += xv * W0[k * FEAT + j];
        }
        #pragma unroll
        for (int k = 0; k < GC; k++) {
            #pragma unroll
            for (int o = 16; o; o >>= 1)
                acc[k] += __shfl_xor_sync(0xffffffffu, acc[k], o);
        }
        if (lane == 0) {
            #pragma unroll
            for (int k = 0; k < GC; k++) g_Ma[row * GC + k] = acc[k];
        }
    }
}

// ---------------------------------------------------------------------------
// K2: out = selu(Ahat @ in) [@ W^T if STAGE<2, else padded stride-12 write]
// ROUND-12 config (53us measured): 256 threads, 16 rows/block, SCALAR A loads
// (float4-A creates 8-way smem conflicts on the Z reads — measured twice).
// ---------------------------------------------------------------------------
#define RPB 16
#define JC  1024
template <int STAGE>
__global__ void k_spmm(const float* __restrict__ A, const float* __restrict__ W) {
    const float* in  = (STAGE == 1) ? g_Mb : g_Ma;
    __shared__ __align__(16) float Zs[JC * 12];
    int rowbase = blockIdx.x * RPB;
    int sub = threadIdx.x & 15;
    int r   = threadIdx.x >> 4;
    int row = rowbase + r;
    float acc[GC];
    #pragma unroll
    for (int k = 0; k < GC; k++) acc[k] = 0.0f;

    for (int jb = 0; jb < NN; jb += JC) {
        __syncthreads();
        for (int t = threadIdx.x; t < JC; t += blockDim.x) {
            int j = jb + t;
            float sj = g_s[j];
            #pragma unroll
            for (int k = 0; k < GC; k++) Zs[t * 12 + k] = sj * in[j * GC + k];
        }
        __syncthreads();
        const float* ar = A + (size_t)row * NN + jb;
        for (int m = 0; m < JC / 16; m++) {
            int jj = sub + m * 16;
            float a = ar[jj];
            float4 z0 = *(const float4*)&Zs[jj * 12];
            float4 z1 = *(const float4*)&Zs[jj * 12 + 4];
            float2 z2 = *(const float2*)&Zs[jj * 12 + 8];
            acc[0] += a * z0.x; acc[1] += a * z0.y;
            acc[2] += a * z0.z; acc[3] += a * z0.w;
            acc[4] += a * z1.x; acc[5] += a * z1.y;
            acc[6] += a * z1.z; acc[7] += a * z1.w;
            acc[8] += a * z2.x; acc[9] += a * z2.y;
        }
    }
    #pragma unroll
    for (int k = 0; k < GC; k++) {
        #pragma unroll
        for (int o = 8; o; o >>= 1)
            acc[k] += __shfl_xor_sync(0xffffffffu, acc[k], o);
    }
    if (sub == 0) {
        float si = g_s[row];
        float sv[GC];
        #pragma unroll
        for (int k = 0; k < GC; k++) {
            float v = si * acc[k] + si * si * in[row * GC + k];
            sv[k] = seluf(v);
        }
        if (STAGE < 2) {
            float* out = (STAGE == 0) ? g_Mb : g_Ma;
            #pragma unroll
            for (int ko = 0; ko < GC; ko++) {
                float s = 0.0f;
                #pragma unroll
                for (int k = 0; k < GC; k++) s = fmaf(sv[k], W[ko * GC + k], s);
                out[row * GC + ko] = s;
            }
        } else {
            #pragma unroll
            for (int k = 0; k < GC; k++) g_Hp[row * 12 + k] = sv[k];
        }
    }
}

// ---------------------------------------------------------------------------
// K3: encoder — wavefront pipeline, packed gate dots, recurrent precomputed,
// sigmoid 0.5-scale folded into i/f/o weight rows (round-13, −130us with dec).
// ---------------------------------------------------------------------------
__global__ void __launch_bounds__(32, 1) k_enc(
    const float* __restrict__ Wih_g, const float* __restrict__ Whh_g,
    const float* __restrict__ bih_g, const float* __restrict__ bhh_g,
    const float* __restrict__ h0_g,  const float* __restrict__ c0_g)
{
    const int lane = threadIdx.x;
    const unsigned FM = 0xffffffffu;
    const int li   = (lane < 30) ? lane : 29;
    const int myl  = li / 10;
    const int rr   = li % 10;
    const int dsel = rr / 5;
    const int j    = rr % 5;
    const int kc   = 2 * myl + dsel;

    const int rI = kc * 20 + j, rF = rI + 5, rG = rI + 10, rO = rI + 15;
    u64 wIF[GC], wGO[GC], vIF[HD], vGO[HD];
    #pragma unroll
    for (int i = 0; i < GC; i++) {
        wIF[i] = pk2(0.5f * Wih_g[rI * GC + i], 0.5f * Wih_g[rF * GC + i]);
        wGO[i] = pk2(Wih_g[rG * GC + i], 0.5f * Wih_g[rO * GC + i]);
    }
    #pragma unroll
    for (int i = 0; i < HD; i++) {
        vIF[i] = pk2(0.5f * Whh_g[rI * HD + i], 0.5f * Whh_g[rF * HD + i]);
        vGO[i] = pk2(Whh_g[rG * HD + i], 0.5f * Whh_g[rO * HD + i]);
    }
    const u64 bIF = pk2(0.5f * (bih_g[rI] + bhh_g[rI]),
                        0.5f * (bih_g[rF] + bhh_g[rF]));
    const u64 bGO = pk2(bih_g[rG] + bhh_g[rG],
                        0.5f * (bih_g[rO] + bhh_g[rO]));

    float h = h0_g[kc * HD + j];
    float c = c0_g[kc * HD + j];
    float hp[HD];
    #pragma unroll
    for (int i = 0; i < HD; i++) hp[i] = h0_g[kc * HD + i];

    u64 rIF = bIF, rGO = bGO;
    #pragma unroll
    for (int i = 0; i < HD; i++) {
        u64 hpk = pk2(hp[i], hp[i]);
        rIF = fma2(vIF[i], hpk, rIF);
        rGO = fma2(vGO[i], hpk, rGO);
    }

    float xin[GC], buf[GC];
    u64 xpk[GC];
    #pragma unroll
    for (int i = 0; i < GC; i++) { xin[i] = g_Hp[i]; xpk[i] = pk2(xin[i], xin[i]); }
    #pragma unroll
    for (int i = 0; i < GC; i++) buf[i] = g_Hp[12 + i];

    const int pullbase = (myl == 0) ? 0 : (myl - 1) * 10;
    const int hpbase   = myl * 10 + dsel * 5;

    for (int w = 0; w < NN + 2; w++) {
        int nrow = (w + 2 < NN) ? (w + 2) : (NN - 1);
        float4 ra = *(const float4*)&g_Hp[nrow * 12];
        float4 rb = *(const float4*)&g_Hp[nrow * 12 + 4];
        float2 rc = *(const float2*)&g_Hp[nrow * 12 + 8];

        bool valid = (w >= myl) && (w - myl < NN);

        u64 s0 = rIF, s1 = 0ull, s2 = rGO, s3 = 0ull;
        #pragma unroll
        for (int i = 0; i < 5; i++) {
            s0 = fma2(wIF[i], xpk[i], s0);
            s2 = fma2(wGO[i], xpk[i], s2);
        }
        #pragma unroll
        for (int i = 5; i < 10; i++) {
            s1 = fma2(wIF[i], xpk[i], s1);
            s3 = fma2(wGO[i], xpk[i], s3);
        }
        u64 gIF = add2(s0, s1), gGO = add2(s2, s3);
        float gi, gf, gg, go;
        upk2(gi, gf, gIF);
        upk2(gg, go, gGO);
        // gi, gf, go are pre-halved via scaled weights
        float ai = fmaf(0.5f, tanha(gi), 0.5f);
        float af = fmaf(0.5f, tanha(gf), 0.5f);
        float ag = tanha(gg);
        float ao = fmaf(0.5f, tanha(go), 0.5f);
        float cn = fmaf(af, c, ai * ag);
        float hn = ao * tanha(cn);
        c = valid ? cn : c;
        h = valid ? hn : h;

        float pull[GC];
        #pragma unroll
        for (int m = 0; m < GC; m++)
            pull[m] = __shfl_sync(FM, h, pullbase + m);
        #pragma unroll
        for (int i = 0; i < HD; i++)
            hp[i] = __shfl_sync(FM, h, hpbase + i);

        #pragma unroll
        for (int m = 0; m < GC; m++) {
            xin[m] = (myl == 0) ? buf[m] : pull[m];
            xpk[m] = pk2(xin[m], xin[m]);
        }
        buf[0] = ra.x; buf[1] = ra.y; buf[2] = ra.z; buf[3] = ra.w;
        buf[4] = rb.x; buf[5] = rb.y; buf[6] = rb.z; buf[7] = rb.w;
        buf[8] = rc.x; buf[9] = rc.y;

        u64 t0 = bIF, t1 = bGO;
        #pragma unroll
        for (int i = 0; i < HD; i++) {
            u64 hpk = pk2(hp[i], hp[i]);
            t0 = fma2(vIF[i], hpk, t0);
            t1 = fma2(vGO[i], hpk, t1);
        }
        rIF = t0; rGO = t1;
    }

    if (lane < 30) {
        g_hfin[lane] = h;
        g_cfin[lane] = c;
    }
}

// ---------------------------------------------------------------------------
// K4: decoder — 20-lane layout, 2 gates/lane packed, recurrent hoisted,
// sigmoid 0.5-scale folded into weights (round-13).
// ---------------------------------------------------------------------------
__global__ void __launch_bounds__(32, 1) k_dec(
    const float* __restrict__ Wih_g, const float* __restrict__ Whh_g,
    const float* __restrict__ bih_g, const float* __restrict__ bhh_g,
    const float* __restrict__ tok_g, const float* __restrict__ Wo_g,
    const float* __restrict__ bo_g,  float* __restrict__ out)
{
    const int lane = threadIdx.x;
    const unsigned FM = 0xffffffffu;
    const int dl  = (lane < 20) ? lane : 19;
    const int pp  = dl % 10;
    const int gh  = dl / 10;   // 0: gates (i,f), 1: gates (g,o)
    const int dd  = pp / 5;
    const int jd  = pp % 5;
    const float sA = gh ? 1.0f : 0.5f;   // A-half input scale

    u64 wAB[3][GC], vAB[3][HD], bAB[3];
    #pragma unroll
    for (int l = 0; l < 3; l++) {
        int kc2  = 2 * l + dd;
        int rowA = kc2 * 20 + gh * 10 + jd;
        int rowB = rowA + 5;
        #pragma unroll
        for (int i = 0; i < GC; i++)
            wAB[l][i] = pk2(sA * Wih_g[rowA * GC + i], 0.5f * Wih_g[rowB * GC + i]);
        #pragma unroll
        for (int i = 0; i < HD; i++)
            vAB[l][i] = pk2(sA * Whh_g[rowA * HD + i], 0.5f * Whh_g[rowB * HD + i]);
        bAB[l] = pk2(sA * (bih_g[rowA] + bhh_g[rowA]),
                     0.5f * (bih_g[rowB] + bhh_g[rowB]));
    }
    float cD[3];
    u64 rAB[3];
    #pragma unroll
    for (int l = 0; l < 3; l++) {
        cD[l] = g_cfin[l * 10 + pp];
        u64 racc = bAB[l];
        #pragma unroll
        for (int i = 0; i < HD; i++) {
            float hv = g_hfin[l * 10 + dd * 5 + i];
            racc = fma2(vAB[l][i], pk2(hv, hv), racc);
        }
        rAB[l] = racc;
    }
    float wov[GC];
    #pragma unroll
    for (int i = 0; i < GC; i++) wov[i] = Wo_g[i];
    const float bo0 = bo_g[0];

    float xs[GC];
    u64 xpk[GC];
    #pragma unroll
    for (int i = 0; i < GC; i++) { xs[i] = tok_g[i]; xpk[i] = pk2(xs[i], xs[i]); }

    for (int t = 0; t < NN; t++) {
        #pragma unroll
        for (int l = 0; l < 3; l++) {
            // critical dot: 10 input terms, packed (A,B) gates
            u64 s0 = rAB[l], s1 = 0ull;
            #pragma unroll
            for (int i = 0; i < 5; i++) s0 = fma2(wAB[l][i], xpk[i], s0);
            #pragma unroll
            for (int i = 5; i < 10; i++) s1 = fma2(wAB[l][i], xpk[i], s1);
            u64 g2 = add2(s0, s1);
            float gA, gB;
            upk2(gA, gB, g2);
            // gh=0: A=i (sig, pre-halved), B=f (sig, pre-halved)
            // gh=1: A=g (tanh, full),      B=o (sig, pre-halved)
            float tA = tanha(gA);
            float aA = gh ? tA : fmaf(0.5f, tA, 0.5f);
            float aB = fmaf(0.5f, tanha(gB), 0.5f);
            float ag = __shfl_sync(FM, aA, 10 + pp);
            float ao = __shfl_sync(FM, aB, 10 + pp);
            float cn = fmaf(aB, cD[l], aA * ag);
            float hn = ao * tanha(cn);
            cD[l] = cn;
            #pragma unroll
            for (int m = 0; m < GC; m++) {
                xs[m] = __shfl_sync(FM, hn, m);
                xpk[m] = pk2(xs[m], xs[m]);
            }
            // precompute next step's recurrent for this layer (off crit path)
            u64 racc = bAB[l];
            #pragma unroll
            for (int i = 0; i < HD; i++) {
                u64 hx = dd ? xpk[5 + i] : xpk[i];
                racc = fma2(vAB[l][i], hx, racc);
            }
            rAB[l] = racc;
        }
        float z = bo0;
        #pragma unroll
        for (int i = 0; i < GC; i++) z = fmaf(xs[i], wov[i], z);
        if (lane == 0) out[t] = siga(z);
    }
}

// ---------------------------------------------------------------------------
extern "C" void kernel_launch(void* const* d_in, const int* in_sizes, int n_in,
                              void* d_out, int out_size)
{
    const float* A   = (const float*)d_in[0];
    const float* X   = (const float*)d_in[1];
    const float* W0  = (const float*)d_in[2];
    const float* W1  = (const float*)d_in[3];
    const float* W2  = (const float*)d_in[4];
    const float* Wih = (const float*)d_in[5];
    const float* Whh = (const float*)d_in[6];
    const float* bih = (const float*)d_in[7];
    const float* bhh = (const float*)d_in[8];
    const float* h0  = (const float*)d_in[9];
    const float* c0  = (const float*)d_in[10];
    const float* tok = (const float*)d_in[11];
    const float* Wo  = (const float*)d_in[12];
    const float* bo  = (const float*)d_in[13];
    float* out = (float*)d_out;
    (void)in_sizes; (void)n_in; (void)out_size;

    k_pre<<<NN + 512, 256>>>(A, X, W0);        // g_s + g_Ma = X@W0^T
    k_spmm<0><<<NN / RPB, 256>>>(A, W1);       // g_Mb = selu(Ahat@g_Ma)@W1^T
    k_spmm<1><<<NN / RPB, 256>>>(A, W2);       // g_Ma = selu(Ahat@g_Mb)@W2^T
    k_spmm<2><<<NN / RPB, 256>>>(A, nullptr);  // g_Hp = H3 (padded)
    k_enc<<<1, 32>>>(Wih, Whh, bih, bhh, h0, c0);
    k_dec<<<1, 32>>>(Wih, Whh, bih, bhh, tok, Wo, bo, out);
}